// round 14
// baseline (speedup 1.0000x reference)
#include <cuda_runtime.h>
#include <cuda_fp16.h>
#include <cstdint>

#define NLEV   3
#define KCODES 512
#define DIM    1024
#define NTOK   65536           // 16 * 4096
#define DECAY  0.99f
#define OMD    0.01f
#define EPSV   1e-5f

typedef unsigned long long ull;
typedef unsigned int       u32;
typedef unsigned short     u16;

// ---- scratch (__device__ globals: the sanctioned no-alloc path) ----
static __device__ __align__(16) u16   g_ah[(size_t)NTOK * DIM];         // 134 MB fp16 hi(resid)
static __device__ __align__(16) u16   g_al[(size_t)NTOK * DIM];         // 134 MB fp16 lo(resid)
static __device__ __align__(16) u16   g_cbh[NLEV * KCODES * DIM];       // 3 MB fp16 hi
static __device__ __align__(16) u16   g_scoreh[(size_t)NTOK * KCODES];  // 67 MB fp16 scores
static __device__ __align__(16) float g_sums[NLEV * KCODES * DIM];      // 6 MB
static __device__ float  g_counts[NLEV * KCODES];
static __device__ float  g_c2[NLEV * KCODES];
static __device__ u32    g_c2max[NLEV];
static __device__ float  g_cs[NLEV * KCODES];
static __device__ float  g_n[NLEV];
static __device__ double g_loss_acc[NLEV];

__device__ __forceinline__ u32 smem_u32(const void* p) {
    u32 a;
    asm("{ .reg .u64 t; cvta.to.shared.u64 t, %1; cvt.u32.u64 %0, t; }" : "=r"(a) : "l"(p));
    return a;
}
__device__ __forceinline__ void red4(float* p, float4 v) {
    asm volatile("red.global.add.v4.f32 [%0], {%1,%2,%3,%4};"
                 :: "l"(p), "f"(v.x), "f"(v.y), "f"(v.z), "f"(v.w) : "memory");
}
__device__ __forceinline__ void ldsm4(u32& r0, u32& r1, u32& r2, u32& r3, u32 addr) {
    asm volatile("ldmatrix.sync.aligned.m8n8.x4.shared.b16 {%0,%1,%2,%3}, [%4];"
                 : "=r"(r0), "=r"(r1), "=r"(r2), "=r"(r3) : "r"(addr));
}
__device__ __forceinline__ void mma16816(float* c, const u32* a, const u32* b) {
    asm volatile("mma.sync.aligned.m16n8k16.row.col.f32.f16.f16.f32 "
                 "{%0,%1,%2,%3}, {%4,%5,%6,%7}, {%8,%9}, {%0,%1,%2,%3};"
                 : "+f"(c[0]), "+f"(c[1]), "+f"(c[2]), "+f"(c[3])
                 : "r"(a[0]), "r"(a[1]), "r"(a[2]), "r"(a[3]), "r"(b[0]), "r"(b[1]));
}
__device__ __forceinline__ void cp16(void* s, const void* g) {
    u32 a = smem_u32(s);
    asm volatile("cp.async.cg.shared.global [%0], [%1], 16;" :: "r"(a), "l"(g));
}
__device__ __forceinline__ void cp_commit() { asm volatile("cp.async.commit_group;"); }
__device__ __forceinline__ void cp_wait1()  { asm volatile("cp.async.wait_group 1;"); }
__device__ __forceinline__ void cp_wait0()  { asm volatile("cp.async.wait_group 0;"); }
// 2-way fp16 split: x = hi + lo exactly to ~2^-22
__device__ __forceinline__ void split2(float x, u16& h, u16& l) {
    __half hh = __float2half_rn(x);
    __half ll = __float2half_rn(x - __half2float(hh));
    h = __half_as_ushort(hh); l = __half_as_ushort(ll);
}
union H8 { u16 s[8]; uint4 v; };

// ---------------------------------------------------------------- zero scratch
__global__ void k_zero() {
    int i = blockIdx.x * blockDim.x + threadIdx.x;
    if (i < NLEV * KCODES * DIM) g_sums[i] = 0.f;
    if (i < NLEV * KCODES)       g_counts[i] = 0.f;
    if (i < NLEV)                { g_loss_acc[i] = 0.0; g_c2max[i] = 0u; }
}

// ------------------------------------------------ codebook fp16-hi + ||C||^2 + max
__global__ void k_cbsplit(const float* __restrict__ codebooks) {
    const int row = blockIdx.x;            // NLEV*KCODES
    const int e0  = threadIdx.x * 8;       // 128 threads
    const float* src = codebooks + (size_t)row * DIM + e0;
    float4 v0 = *(const float4*)src;
    float4 v1 = *(const float4*)(src + 4);
    float xs[8] = {v0.x, v0.y, v0.z, v0.w, v1.x, v1.y, v1.z, v1.w};
    H8 ph;
    float s = 0.f;
#pragma unroll
    for (int i = 0; i < 8; i++) {
        s += xs[i] * xs[i];
        ph.s[i] = __half_as_ushort(__float2half_rn(xs[i]));
    }
    *(uint4*)(g_cbh + (size_t)row * DIM + e0) = ph.v;
#pragma unroll
    for (int o = 16; o; o >>= 1) s += __shfl_xor_sync(0xffffffffu, s, o);
    __shared__ float red[4];
    if ((threadIdx.x & 31) == 0) red[threadIdx.x >> 5] = s;
    __syncthreads();
    if (threadIdx.x == 0) {
        float c2 = red[0] + red[1] + red[2] + red[3];
        g_c2[row] = c2;
        atomicMax(&g_c2max[row >> 9], __float_as_uint(c2));   // c2 >= 0
    }
}

// ---------------------------------------------------------------- phase 1: hh scores
// Block: 64 tokens x 512 codes (4 ct tiles of 128). 8 warps: mw=wid&1 (32-token
// slice), nw=wid>>1 (32-code slice). cp.async double-buffered 64-k chunks.
// Level 0 stages A from z_e (f32) with LDG+cvt+STS; levels 1-2 from g_ah.
#define ASTRIDE 72
#define SA_ELE (64 * ASTRIDE)      // 4608 halves
#define SB_ELE (128 * ASTRIDE)     // 9216 halves
#define BUF_ELE (SA_ELE + SB_ELE)  // 13824 halves = 27648 B
#define SMEM_SCORE (2 * BUF_ELE * 2)   // 55296 B

__global__ void __launch_bounds__(256, 3) k_score(int level, const float* __restrict__ z_e) {
    extern __shared__ __align__(16) u16 dsm[];

    const int tid = threadIdx.x, wid = tid >> 5, lane = tid & 31;
    const int mw = wid & 1, nw = wid >> 1;
    const int t0 = blockIdx.x * 64;
    const bool lvl0 = (level == 0);

    const u16* bh = g_cbh + (size_t)level * KCODES * DIM;
    const float* c2p = g_c2 + level * KCODES;

    const int srow = tid >> 3, sg = tid & 7;

    // ldmatrix addressing
    const int aro = mw * 32 + (lane & 15);         // + mg*16
    const int aco = (lane >> 4) * 8;               // + k0
    const int matid = lane >> 3;
    const int selj = matid >> 1, selk = matid & 1;
    const int bro = nw * 32 + selj * 8 + (lane & 7);  // + jp*16
    const int bco = selk * 8;                          // + k0

    // stage chunk it = ct*16 + kc into buffer b
    auto stage = [&](int it, int b) {
        const int ct = it >> 4, d0 = (it & 15) * 64;
        u16* bufA = dsm + b * BUF_ELE;
        u16* bufB = bufA + SA_ELE;
        if (lvl0) {
#pragma unroll
            for (int i = 0; i < 2; i++) {
                int r = srow + i * 32;
                const float* src = z_e + (size_t)(t0 + r) * DIM + d0 + sg * 8;
                float4 v0 = __ldg((const float4*)src);
                float4 v1 = __ldg((const float4*)(src + 4));
                H8 ph;
                ph.s[0] = __half_as_ushort(__float2half_rn(v0.x));
                ph.s[1] = __half_as_ushort(__float2half_rn(v0.y));
                ph.s[2] = __half_as_ushort(__float2half_rn(v0.z));
                ph.s[3] = __half_as_ushort(__float2half_rn(v0.w));
                ph.s[4] = __half_as_ushort(__float2half_rn(v1.x));
                ph.s[5] = __half_as_ushort(__float2half_rn(v1.y));
                ph.s[6] = __half_as_ushort(__float2half_rn(v1.z));
                ph.s[7] = __half_as_ushort(__float2half_rn(v1.w));
                *(uint4*)&bufA[r * ASTRIDE + sg * 8] = ph.v;
            }
        } else {
#pragma unroll
            for (int i = 0; i < 2; i++) {
                int r = srow + i * 32;
                cp16(&bufA[r * ASTRIDE + sg * 8], g_ah + (size_t)(t0 + r) * DIM + d0 + sg * 8);
            }
        }
#pragma unroll
        for (int i = 0; i < 4; i++) {
            int r = srow + i * 32;
            cp16(&bufB[r * ASTRIDE + sg * 8], bh + (size_t)(ct * 128 + r) * DIM + d0 + sg * 8);
        }
        cp_commit();
    };

    float c[2][4][4];
#pragma unroll
    for (int mg = 0; mg < 2; mg++)
#pragma unroll
        for (int ng = 0; ng < 4; ng++)
#pragma unroll
            for (int q = 0; q < 4; q++) c[mg][ng][q] = 0.f;

    stage(0, 0);

    for (int it = 0; it < 64; it++) {
        const int b = it & 1;
        if (it + 1 < 64) { stage(it + 1, b ^ 1); cp_wait1(); } else { cp_wait0(); }
        __syncthreads();                        // buffer b ready for all warps

        const u32 aA = smem_u32(dsm + b * BUF_ELE);
        const u32 aB = smem_u32(dsm + b * BUF_ELE + SA_ELE);
#pragma unroll
        for (int kk = 0; kk < 4; kk++) {
            const int k0 = kk * 16;
            u32 Am[2][4];
#pragma unroll
            for (int mg = 0; mg < 2; mg++)
                ldsm4(Am[mg][0], Am[mg][1], Am[mg][2], Am[mg][3],
                      aA + (u32)(((aro + mg * 16) * ASTRIDE + aco + k0) * 2));
#pragma unroll
            for (int jp = 0; jp < 2; jp++) {
                u32 Bf[4];
                ldsm4(Bf[0], Bf[1], Bf[2], Bf[3],
                      aB + (u32)(((bro + jp * 16) * ASTRIDE + bco + k0) * 2));
#pragma unroll
                for (int mg = 0; mg < 2; mg++) {
                    mma16816(c[mg][2 * jp],     Am[mg], &Bf[0]);
                    mma16816(c[mg][2 * jp + 1], Am[mg], &Bf[2]);
                }
            }
        }

        if ((it & 15) == 15) {
            // epilogue for this 128-code tile: fp16 scores
            const int ct = it >> 4;
#pragma unroll
            for (int mg = 0; mg < 2; mg++) {
                const int row0 = t0 + mw * 32 + mg * 16 + (lane >> 2);
#pragma unroll
                for (int ng = 0; ng < 4; ng++) {
                    const int id = ct * 128 + nw * 32 + ng * 8 + 2 * (lane & 3);
                    const float c2a = __ldg(c2p + id);
                    const float c2b = __ldg(c2p + id + 1);
                    __half2 pa = __floats2half2_rn(c2a - 2.f * c[mg][ng][0], c2b - 2.f * c[mg][ng][1]);
                    __half2 pb = __floats2half2_rn(c2a - 2.f * c[mg][ng][2], c2b - 2.f * c[mg][ng][3]);
                    *(u32*)(g_scoreh + (size_t)row0 * KCODES + id)       = *(u32*)&pa;
                    *(u32*)(g_scoreh + (size_t)(row0 + 8) * KCODES + id) = *(u32*)&pb;
#pragma unroll
                    for (int q = 0; q < 4; q++) c[mg][ng][q] = 0.f;
                }
            }
        }
        __syncthreads();                        // all reads of buffer b done
    }
}

// ---------------------------------------------------------------- phase 2: pick + update (fused)
// One warp per token. 4 CTAs/SM (<=64 regs): scores re-read from L1 in the
// ballot pass (no register cache); update epilogue processes 8-dim groups so
// split registers stay short-lived.
__global__ void __launch_bounds__(256, 4) k_pick(int level,
                                                 const float* __restrict__ z_e,
                                                 const float* __restrict__ codebooks,
                                                 float* __restrict__ out_zq,
                                                 float* __restrict__ out_idx) {
    const int wid = threadIdx.x >> 5, lane = threadIdx.x & 31;
    const int tok = blockIdx.x * 8 + wid;
    const float* c2p = g_c2 + level * KCODES;
    const float* cbl = codebooks + (size_t)level * KCODES * DIM;
    const u16* srow = g_scoreh + (size_t)tok * KCODES;

    // pass 1: min over fp16 scores (lane covers codes lane*4 + i*128 + 0..3)
    float mv = 3.4e38f; int mi = 0;
#pragma unroll
    for (int i = 0; i < 4; i++) {
        uint2 pv = *(const uint2*)(srow + lane * 4 + i * 128);
        float2 f0 = __half22float2(*(__half2*)&pv.x);
        float2 f1 = __half22float2(*(__half2*)&pv.y);
        const int c0 = lane * 4 + i * 128;
        if (f0.x < mv || (f0.x == mv && c0     < mi)) { mv = f0.x; mi = c0; }
        if (f0.y < mv || (f0.y == mv && c0 + 1 < mi)) { mv = f0.y; mi = c0 + 1; }
        if (f1.x < mv || (f1.x == mv && c0 + 2 < mi)) { mv = f1.x; mi = c0 + 2; }
        if (f1.y < mv || (f1.y == mv && c0 + 3 < mi)) { mv = f1.y; mi = c0 + 3; }
    }
#pragma unroll
    for (int o = 16; o; o >>= 1) {
        float ov = __shfl_xor_sync(0xffffffffu, mv, o);
        int   oi = __shfl_xor_sync(0xffffffffu, mi, o);
        if (ov < mv || (ov == mv && oi < mi)) { mv = ov; mi = oi; }
    }

    // residual: lane holds dims [lane*32, lane*32+32)
    float4 r4[8];
    float r2 = 0.f;
    if (level == 0) {
        const float* rin = z_e + (size_t)tok * DIM + lane * 32;
#pragma unroll
        for (int v = 0; v < 8; v++) r4[v] = *(const float4*)(rin + v * 4);
    } else {
        const u16* ap = g_ah + (size_t)tok * DIM + lane * 32;
        const u16* lp = g_al + (size_t)tok * DIM + lane * 32;
#pragma unroll
        for (int g = 0; g < 4; g++) {
            uint4 hv = *(const uint4*)(ap + g * 8);
            uint4 lv = *(const uint4*)(lp + g * 8);
            const __half2* hh = (const __half2*)&hv;
            const __half2* ll = (const __half2*)&lv;
            float2 a0 = __half22float2(hh[0]), b0 = __half22float2(ll[0]);
            float2 a1 = __half22float2(hh[1]), b1 = __half22float2(ll[1]);
            float2 a2 = __half22float2(hh[2]), b2 = __half22float2(ll[2]);
            float2 a3 = __half22float2(hh[3]), b3 = __half22float2(ll[3]);
            r4[2 * g]     = make_float4(a0.x + b0.x, a0.y + b0.y, a1.x + b1.x, a1.y + b1.y);
            r4[2 * g + 1] = make_float4(a2.x + b2.x, a2.y + b2.y, a3.x + b3.x, a3.y + b3.y);
        }
    }
#pragma unroll
    for (int v = 0; v < 8; v++)
        r2 += r4[v].x * r4[v].x + r4[v].y * r4[v].y + r4[v].z * r4[v].z + r4[v].w * r4[v].w;
#pragma unroll
    for (int o = 16; o; o >>= 1) r2 += __shfl_xor_sync(0xffffffffu, r2, o);

    const float c2mx = __uint_as_float(g_c2max[level]);
    const float cmax = sqrtf(c2mx);
    const float rn   = sqrtf(r2);
    const float smax = c2mx + 2.f * rn * cmax;               // bound on |score|
    const float thr  = mv + 0.0039f * rn * cmax + 0.001f * smax + 0.5f;

    // pass 2: re-read scores (L1-hot), exact fp32 rescore of candidates
    float bestv = 3.4e38f; int besti = 0;
#pragma unroll
    for (int i = 0; i < 4; i++) {
        uint2 pv = *(const uint2*)(srow + lane * 4 + i * 128);
        float2 f0 = __half22float2(*(__half2*)&pv.x);
        float2 f1 = __half22float2(*(__half2*)&pv.y);
        float sv[4] = {f0.x, f0.y, f1.x, f1.y};
#pragma unroll
        for (int j = 0; j < 4; j++) {
            const int cid_l = lane * 4 + i * 128 + j;
            u32 m = __ballot_sync(0xffffffffu, sv[j] <= thr);
            while (m) {
                const int src = __ffs(m) - 1; m &= m - 1;
                const int cid = __shfl_sync(0xffffffffu, cid_l, src);
                const float* crow = cbl + (size_t)cid * DIM + lane * 32;
                float dot = 0.f;
#pragma unroll
                for (int v = 0; v < 8; v++) {
                    float4 q = __ldg((const float4*)(crow + v * 4));
                    dot += r4[v].x * q.x + r4[v].y * q.y + r4[v].z * q.z + r4[v].w * q.w;
                }
#pragma unroll
                for (int o = 16; o; o >>= 1) dot += __shfl_xor_sync(0xffffffffu, dot, o);
                const float sc = __ldg(c2p + cid) - 2.f * dot;
                if (sc < bestv || (sc == bestv && cid < besti)) { bestv = sc; besti = cid; }
            }
        }
    }

    // ---- fused update (per-8-dim groups; short register lifetimes) ----
    const float* qrow = cbl + (size_t)besti * DIM + lane * 32;
    float* sums = g_sums + ((size_t)(level * KCODES + besti)) * DIM + lane * 32;
    const float* zrow = z_e + (size_t)tok * DIM + lane * 32;
    float* zo = out_zq + (size_t)tok * DIM + lane * 32;
    u16* ao = g_ah + (size_t)tok * DIM + lane * 32;
    u16* lo = g_al + (size_t)tok * DIM + lane * 32;

    float ls = 0.f;
#pragma unroll
    for (int g = 0; g < 4; g++) {
        float4 q0 = __ldg((const float4*)(qrow + g * 8));
        float4 q1 = __ldg((const float4*)(qrow + g * 8 + 4));
        float4 ra = r4[2 * g], rb = r4[2 * g + 1];
        float4 rq0 = make_float4(ra.x - q0.x, ra.y - q0.y, ra.z - q0.z, ra.w - q0.w);
        float4 rq1 = make_float4(rb.x - q1.x, rb.y - q1.y, rb.z - q1.z, rb.w - q1.w);
        ls += rq0.x * rq0.x + rq0.y * rq0.y + rq0.z * rq0.z + rq0.w * rq0.w
            + rq1.x * rq1.x + rq1.y * rq1.y + rq1.z * rq1.z + rq1.w * rq1.w;
        if (level < 2) {
            H8 ph, pl;
            split2(rq0.x, ph.s[0], pl.s[0]);
            split2(rq0.y, ph.s[1], pl.s[1]);
            split2(rq0.z, ph.s[2], pl.s[2]);
            split2(rq0.w, ph.s[3], pl.s[3]);
            split2(rq1.x, ph.s[4], pl.s[4]);
            split2(rq1.y, ph.s[5], pl.s[5]);
            split2(rq1.z, ph.s[6], pl.s[6]);
            split2(rq1.w, ph.s[7], pl.s[7]);
            *(uint4*)(ao + g * 8) = ph.v;
            *(uint4*)(lo + g * 8) = pl.v;
        } else {
            float4 z0 = __ldg((const float4*)(zrow + g * 8));
            float4 z1 = __ldg((const float4*)(zrow + g * 8 + 4));
            *(float4*)(zo + g * 8)     = make_float4(z0.x - rq0.x, z0.y - rq0.y, z0.z - rq0.z, z0.w - rq0.w);
            *(float4*)(zo + g * 8 + 4) = make_float4(z1.x - rq1.x, z1.y - rq1.y, z1.z - rq1.z, z1.w - rq1.w);
        }
        red4(sums + g * 8, ra);
        red4(sums + g * 8 + 4, rb);
    }
    if (lane == 0) {
        atomicAdd(g_counts + level * KCODES + besti, 1.0f);
        out_idx[(size_t)level * NTOK + tok] = (float)besti;
    }

    // block loss reduction -> one double atomic
#pragma unroll
    for (int o = 16; o; o >>= 1) ls += __shfl_xor_sync(0xffffffffu, ls, o);
    __shared__ float red[8];
    if (lane == 0) red[wid] = ls;
    __syncthreads();
    if (threadIdx.x < 8) {
        float v = red[threadIdx.x];
#pragma unroll
        for (int o = 4; o; o >>= 1) v += __shfl_xor_sync(0xffu, v, o);
        if (threadIdx.x == 0) atomicAdd(&g_loss_acc[level], (double)v);
    }
}

// ---------------------------------------------------------------- cs + n
__global__ void k_csn(const float* __restrict__ ema_cluster) {
    const int l = blockIdx.x;
    const int k = threadIdx.x;   // 512 threads
    float cs = DECAY * ema_cluster[l * KCODES + k] + OMD * g_counts[l * KCODES + k];
    g_cs[l * KCODES + k] = cs;
    float s = cs;
#pragma unroll
    for (int o = 16; o; o >>= 1) s += __shfl_xor_sync(0xffffffffu, s, o);
    __shared__ float red[16];
    const int warp = threadIdx.x >> 5, lane = threadIdx.x & 31;
    if (lane == 0) red[warp] = s;
    __syncthreads();
    if (threadIdx.x < 16) {
        float v = red[threadIdx.x];
#pragma unroll
        for (int o = 8; o; o >>= 1) v += __shfl_xor_sync(0xffffu, v, o);
        if (threadIdx.x == 0) g_n[l] = v;
    }
}

// ---------------------------------------------------------------- new codebooks + loss
__global__ void k_cb(const float* __restrict__ ema_w,
                     float* __restrict__ out_cb,
                     float* __restrict__ out_loss) {
    const int i = blockIdx.x * blockDim.x + threadIdx.x;
    if (i == 0) {
        double L = (0.25 * g_loss_acc[0] + 0.5 * g_loss_acc[1] + 1.0 * g_loss_acc[2])
                   * (1.0 / ((double)NTOK * (double)DIM));
        *out_loss = (float)L;
    }
    if (i >= NLEV * KCODES * DIM) return;
    const int row = i >> 10;
    const int l   = row >> 9;
    float w  = DECAY * ema_w[i] + OMD * g_sums[i];
    float cs = g_cs[row];
    float n  = g_n[l];
    float csn = (cs + EPSV) / (n + 0.00512f) * n;   // K*EPS = 512e-5
    out_cb[i] = w / csn;
}

// ---------------------------------------------------------------- launch
extern "C" void kernel_launch(void* const* d_in, const int* in_sizes, int n_in,
                              void* d_out, int out_size) {
    const float* z_e         = (const float*)d_in[0];
    const float* codebooks   = (const float*)d_in[1];
    const float* ema_cluster = (const float*)d_in[2];
    const float* ema_w       = (const float*)d_in[3];
    float* out = (float*)d_out;

    const size_t ZQ = (size_t)NTOK * DIM;
    float* out_zq   = out;
    float* out_loss = out + ZQ;
    float* out_idx  = out + ZQ + 1;
    float* out_cb   = out + ZQ + 1 + (size_t)NLEV * NTOK;

    cudaFuncSetAttribute(k_score, cudaFuncAttributeMaxDynamicSharedMemorySize, SMEM_SCORE);

    k_zero<<<(NLEV * KCODES * DIM + 255) / 256, 256>>>();
    k_cbsplit<<<NLEV * KCODES, 128>>>(codebooks);
    for (int l = 0; l < NLEV; l++) {
        k_score<<<NTOK / 64, 256, SMEM_SCORE>>>(l, z_e);
        k_pick<<<NTOK / 8, 256>>>(l, z_e, codebooks, out_zq, out_idx);
    }
    k_csn<<<NLEV, 512>>>(ema_cluster);
    k_cb<<<(NLEV * KCODES * DIM + 255) / 256, 256>>>(ema_w, out_cb, out_loss);
}

// round 15
// speedup vs baseline: 1.0307x; 1.0307x over previous
#include <cuda_runtime.h>
#include <cuda_fp16.h>
#include <cstdint>

#define NLEV   3
#define KCODES 512
#define DIM    1024
#define NTOK   65536           // 16 * 4096
#define DECAY  0.99f
#define OMD    0.01f
#define EPSV   1e-5f

typedef unsigned long long ull;
typedef unsigned int       u32;
typedef unsigned short     u16;

// ---- scratch (__device__ globals: the sanctioned no-alloc path) ----
static __device__ __align__(16) u16   g_ah[(size_t)NTOK * DIM];         // 134 MB fp16 hi(resid)
static __device__ __align__(16) u16   g_al[(size_t)NTOK * DIM];         // 134 MB fp16 lo(resid)
static __device__ __align__(16) u16   g_cbh[NLEV * KCODES * DIM];       // 3 MB fp16 hi
static __device__ __align__(16) u16   g_scoreh[(size_t)NTOK * KCODES];  // 67 MB fp16 scores
static __device__ __align__(16) float g_sums[NLEV * KCODES * DIM];      // 6 MB
static __device__ float  g_counts[NLEV * KCODES];
static __device__ float  g_c2[NLEV * KCODES];
static __device__ u32    g_c2max[NLEV];
static __device__ float  g_cs[NLEV * KCODES];
static __device__ float  g_n[NLEV];
static __device__ double g_loss_acc[NLEV];

__device__ __forceinline__ u32 smem_u32(const void* p) {
    u32 a;
    asm("{ .reg .u64 t; cvta.to.shared.u64 t, %1; cvt.u32.u64 %0, t; }" : "=r"(a) : "l"(p));
    return a;
}
__device__ __forceinline__ void red4(float* p, float4 v) {
    asm volatile("red.global.add.v4.f32 [%0], {%1,%2,%3,%4};"
                 :: "l"(p), "f"(v.x), "f"(v.y), "f"(v.z), "f"(v.w) : "memory");
}
__device__ __forceinline__ void ldsm4(u32& r0, u32& r1, u32& r2, u32& r3, u32 addr) {
    asm volatile("ldmatrix.sync.aligned.m8n8.x4.shared.b16 {%0,%1,%2,%3}, [%4];"
                 : "=r"(r0), "=r"(r1), "=r"(r2), "=r"(r3) : "r"(addr));
}
__device__ __forceinline__ void mma16816(float* c, const u32* a, const u32* b) {
    asm volatile("mma.sync.aligned.m16n8k16.row.col.f32.f16.f16.f32 "
                 "{%0,%1,%2,%3}, {%4,%5,%6,%7}, {%8,%9}, {%0,%1,%2,%3};"
                 : "+f"(c[0]), "+f"(c[1]), "+f"(c[2]), "+f"(c[3])
                 : "r"(a[0]), "r"(a[1]), "r"(a[2]), "r"(a[3]), "r"(b[0]), "r"(b[1]));
}
__device__ __forceinline__ void cp16(void* s, const void* g) {
    u32 a = smem_u32(s);
    asm volatile("cp.async.cg.shared.global [%0], [%1], 16;" :: "r"(a), "l"(g));
}
__device__ __forceinline__ void cp_commit() { asm volatile("cp.async.commit_group;"); }
__device__ __forceinline__ void cp_wait1()  { asm volatile("cp.async.wait_group 1;"); }
__device__ __forceinline__ void cp_wait0()  { asm volatile("cp.async.wait_group 0;"); }
// 2-way fp16 split: x = hi + lo exactly to ~2^-22
__device__ __forceinline__ void split2(float x, u16& h, u16& l) {
    __half hh = __float2half_rn(x);
    __half ll = __float2half_rn(x - __half2float(hh));
    h = __half_as_ushort(hh); l = __half_as_ushort(ll);
}
union H8 { u16 s[8]; uint4 v; };

// ---------------------------------------------------------------- zero scratch
__global__ void k_zero() {
    int i = blockIdx.x * blockDim.x + threadIdx.x;
    if (i < NLEV * KCODES * DIM) g_sums[i] = 0.f;
    if (i < NLEV * KCODES)       g_counts[i] = 0.f;
    if (i < NLEV)                { g_loss_acc[i] = 0.0; g_c2max[i] = 0u; }
}

// ------------------------------------------------ codebook fp16-hi + ||C||^2 + max
__global__ void k_cbsplit(const float* __restrict__ codebooks) {
    const int row = blockIdx.x;            // NLEV*KCODES
    const int e0  = threadIdx.x * 8;       // 128 threads
    const float* src = codebooks + (size_t)row * DIM + e0;
    float4 v0 = *(const float4*)src;
    float4 v1 = *(const float4*)(src + 4);
    float xs[8] = {v0.x, v0.y, v0.z, v0.w, v1.x, v1.y, v1.z, v1.w};
    H8 ph;
    float s = 0.f;
#pragma unroll
    for (int i = 0; i < 8; i++) {
        s += xs[i] * xs[i];
        ph.s[i] = __half_as_ushort(__float2half_rn(xs[i]));
    }
    *(uint4*)(g_cbh + (size_t)row * DIM + e0) = ph.v;
#pragma unroll
    for (int o = 16; o; o >>= 1) s += __shfl_xor_sync(0xffffffffu, s, o);
    __shared__ float red[4];
    if ((threadIdx.x & 31) == 0) red[threadIdx.x >> 5] = s;
    __syncthreads();
    if (threadIdx.x == 0) {
        float c2 = red[0] + red[1] + red[2] + red[3];
        g_c2[row] = c2;
        atomicMax(&g_c2max[row >> 9], __float_as_uint(c2));   // c2 >= 0
    }
}

// ---------------------------------------------------------------- phase 1: hh scores
// Block: 64 tokens x 512 codes (4 ct tiles of 128). 8 warps: mw=wid&1 (32-token
// slice), nw=wid>>1 (32-code slice). cp.async double-buffered 64-k chunks.
// Level 0 stages A from z_e (f32) with LDG+cvt+STS; levels 1-2 from g_ah.
#define ASTRIDE 72
#define SA_ELE (64 * ASTRIDE)      // 4608 halves
#define SB_ELE (128 * ASTRIDE)     // 9216 halves
#define BUF_ELE (SA_ELE + SB_ELE)  // 13824 halves = 27648 B
#define SMEM_SCORE (2 * BUF_ELE * 2)   // 55296 B

__global__ void __launch_bounds__(256, 3) k_score(int level, const float* __restrict__ z_e) {
    extern __shared__ __align__(16) u16 dsm[];

    const int tid = threadIdx.x, wid = tid >> 5, lane = tid & 31;
    const int mw = wid & 1, nw = wid >> 1;
    const int t0 = blockIdx.x * 64;
    const bool lvl0 = (level == 0);

    const u16* bh = g_cbh + (size_t)level * KCODES * DIM;
    const float* c2p = g_c2 + level * KCODES;

    const int srow = tid >> 3, sg = tid & 7;

    // ldmatrix addressing
    const int aro = mw * 32 + (lane & 15);         // + mg*16
    const int aco = (lane >> 4) * 8;               // + k0
    const int matid = lane >> 3;
    const int selj = matid >> 1, selk = matid & 1;
    const int bro = nw * 32 + selj * 8 + (lane & 7);  // + jp*16
    const int bco = selk * 8;                          // + k0

    // stage chunk it = ct*16 + kc into buffer b
    auto stage = [&](int it, int b) {
        const int ct = it >> 4, d0 = (it & 15) * 64;
        u16* bufA = dsm + b * BUF_ELE;
        u16* bufB = bufA + SA_ELE;
        if (lvl0) {
#pragma unroll
            for (int i = 0; i < 2; i++) {
                int r = srow + i * 32;
                const float* src = z_e + (size_t)(t0 + r) * DIM + d0 + sg * 8;
                float4 v0 = __ldg((const float4*)src);
                float4 v1 = __ldg((const float4*)(src + 4));
                H8 ph;
                ph.s[0] = __half_as_ushort(__float2half_rn(v0.x));
                ph.s[1] = __half_as_ushort(__float2half_rn(v0.y));
                ph.s[2] = __half_as_ushort(__float2half_rn(v0.z));
                ph.s[3] = __half_as_ushort(__float2half_rn(v0.w));
                ph.s[4] = __half_as_ushort(__float2half_rn(v1.x));
                ph.s[5] = __half_as_ushort(__float2half_rn(v1.y));
                ph.s[6] = __half_as_ushort(__float2half_rn(v1.z));
                ph.s[7] = __half_as_ushort(__float2half_rn(v1.w));
                *(uint4*)&bufA[r * ASTRIDE + sg * 8] = ph.v;
            }
        } else {
#pragma unroll
            for (int i = 0; i < 2; i++) {
                int r = srow + i * 32;
                cp16(&bufA[r * ASTRIDE + sg * 8], g_ah + (size_t)(t0 + r) * DIM + d0 + sg * 8);
            }
        }
#pragma unroll
        for (int i = 0; i < 4; i++) {
            int r = srow + i * 32;
            cp16(&bufB[r * ASTRIDE + sg * 8], bh + (size_t)(ct * 128 + r) * DIM + d0 + sg * 8);
        }
        cp_commit();
    };

    float c[2][4][4];
#pragma unroll
    for (int mg = 0; mg < 2; mg++)
#pragma unroll
        for (int ng = 0; ng < 4; ng++)
#pragma unroll
            for (int q = 0; q < 4; q++) c[mg][ng][q] = 0.f;

    stage(0, 0);

    for (int it = 0; it < 64; it++) {
        const int b = it & 1;
        if (it + 1 < 64) { stage(it + 1, b ^ 1); cp_wait1(); } else { cp_wait0(); }
        __syncthreads();                        // buffer b ready for all warps

        const u32 aA = smem_u32(dsm + b * BUF_ELE);
        const u32 aB = smem_u32(dsm + b * BUF_ELE + SA_ELE);
#pragma unroll
        for (int kk = 0; kk < 4; kk++) {
            const int k0 = kk * 16;
            u32 Am[2][4];
#pragma unroll
            for (int mg = 0; mg < 2; mg++)
                ldsm4(Am[mg][0], Am[mg][1], Am[mg][2], Am[mg][3],
                      aA + (u32)(((aro + mg * 16) * ASTRIDE + aco + k0) * 2));
#pragma unroll
            for (int jp = 0; jp < 2; jp++) {
                u32 Bf[4];
                ldsm4(Bf[0], Bf[1], Bf[2], Bf[3],
                      aB + (u32)(((bro + jp * 16) * ASTRIDE + bco + k0) * 2));
#pragma unroll
                for (int mg = 0; mg < 2; mg++) {
                    mma16816(c[mg][2 * jp],     Am[mg], &Bf[0]);
                    mma16816(c[mg][2 * jp + 1], Am[mg], &Bf[2]);
                }
            }
        }

        if ((it & 15) == 15) {
            // epilogue for this 128-code tile: fp16 scores
            const int ct = it >> 4;
#pragma unroll
            for (int mg = 0; mg < 2; mg++) {
                const int row0 = t0 + mw * 32 + mg * 16 + (lane >> 2);
#pragma unroll
                for (int ng = 0; ng < 4; ng++) {
                    const int id = ct * 128 + nw * 32 + ng * 8 + 2 * (lane & 3);
                    const float c2a = __ldg(c2p + id);
                    const float c2b = __ldg(c2p + id + 1);
                    __half2 pa = __floats2half2_rn(c2a - 2.f * c[mg][ng][0], c2b - 2.f * c[mg][ng][1]);
                    __half2 pb = __floats2half2_rn(c2a - 2.f * c[mg][ng][2], c2b - 2.f * c[mg][ng][3]);
                    *(u32*)(g_scoreh + (size_t)row0 * KCODES + id)       = *(u32*)&pa;
                    *(u32*)(g_scoreh + (size_t)(row0 + 8) * KCODES + id) = *(u32*)&pb;
#pragma unroll
                    for (int q = 0; q < 4; q++) c[mg][ng][q] = 0.f;
                }
            }
        }
        __syncthreads();                        // all reads of buffer b done
    }
}

// ---------------------------------------------------------------- phase 2: pick + update (fused)
// One warp per token. Scores register-cached from 2 uint4 loads (16 codes/lane);
// tightened rigorous margin; exact fp32 rescore of candidates; fused update.
__global__ void __launch_bounds__(256, 3) k_pick(int level,
                                                 const float* __restrict__ z_e,
                                                 const float* __restrict__ codebooks,
                                                 float* __restrict__ out_zq,
                                                 float* __restrict__ out_idx) {
    const int wid = threadIdx.x >> 5, lane = threadIdx.x & 31;
    const int tok = blockIdx.x * 8 + wid;
    const float* c2p = g_c2 + level * KCODES;
    const float* cbl = codebooks + (size_t)level * KCODES * DIM;
    const u16* srow = g_scoreh + (size_t)tok * KCODES;

    // scores: lane covers codes {i*256 + lane*8 + 0..7}, i in {0,1} -> 2 uint4 loads
    float s[16];
    float mv = 3.4e38f; int mi = 0;
#pragma unroll
    for (int i = 0; i < 2; i++) {
        uint4 pv = *(const uint4*)(srow + i * 256 + lane * 8);
        const u32 w[4] = {pv.x, pv.y, pv.z, pv.w};
        const int c0 = i * 256 + lane * 8;
#pragma unroll
        for (int h = 0; h < 4; h++) {
            float2 f = __half22float2(*(const __half2*)&w[h]);
            s[i * 8 + 2 * h]     = f.x;
            s[i * 8 + 2 * h + 1] = f.y;
            const int ca = c0 + 2 * h;
            if (f.x < mv || (f.x == mv && ca     < mi)) { mv = f.x; mi = ca; }
            if (f.y < mv || (f.y == mv && ca + 1 < mi)) { mv = f.y; mi = ca + 1; }
        }
    }
#pragma unroll
    for (int o = 16; o; o >>= 1) {
        float ov = __shfl_xor_sync(0xffffffffu, mv, o);
        int   oi = __shfl_xor_sync(0xffffffffu, mi, o);
        if (ov < mv || (ov == mv && oi < mi)) { mv = ov; mi = oi; }
    }

    // residual: lane holds dims [lane*32, lane*32+32)
    float4 r4[8];
    float r2 = 0.f;
    if (level == 0) {
        const float* rin = z_e + (size_t)tok * DIM + lane * 32;
#pragma unroll
        for (int v = 0; v < 8; v++) r4[v] = *(const float4*)(rin + v * 4);
    } else {
        const u16* ap = g_ah + (size_t)tok * DIM + lane * 32;
        const u16* lp = g_al + (size_t)tok * DIM + lane * 32;
#pragma unroll
        for (int g = 0; g < 4; g++) {
            uint4 hv = *(const uint4*)(ap + g * 8);
            uint4 lv = *(const uint4*)(lp + g * 8);
            const __half2* hh = (const __half2*)&hv;
            const __half2* ll = (const __half2*)&lv;
            float2 a0 = __half22float2(hh[0]), b0 = __half22float2(ll[0]);
            float2 a1 = __half22float2(hh[1]), b1 = __half22float2(ll[1]);
            float2 a2 = __half22float2(hh[2]), b2 = __half22float2(ll[2]);
            float2 a3 = __half22float2(hh[3]), b3 = __half22float2(ll[3]);
            r4[2 * g]     = make_float4(a0.x + b0.x, a0.y + b0.y, a1.x + b1.x, a1.y + b1.y);
            r4[2 * g + 1] = make_float4(a2.x + b2.x, a2.y + b2.y, a3.x + b3.x, a3.y + b3.y);
        }
    }
#pragma unroll
    for (int v = 0; v < 8; v++)
        r2 += r4[v].x * r4[v].x + r4[v].y * r4[v].y + r4[v].z * r4[v].z + r4[v].w * r4[v].w;
#pragma unroll
    for (int o = 16; o; o >>= 1) r2 += __shfl_xor_sync(0xffffffffu, r2, o);

    // rigorous margin: 2*eps_hh + 2q*(|mv|+8) + fp32-accum slop
    const float c2mx = __uint_as_float(g_c2max[level]);
    const float cmax = sqrtf(c2mx);
    const float rn   = sqrtf(r2);
    const float thr  = mv + 0.0039f * rn * cmax + 0.000977f * (fabsf(mv) + 8.f) + 0.25f;

    // exact rescore of candidates
    float bestv = 3.4e38f; int besti = 0;
#pragma unroll
    for (int i = 0; i < 16; i++) {
        const int cid_l = (i >> 3) * 256 + lane * 8 + (i & 7);
        u32 m = __ballot_sync(0xffffffffu, s[i] <= thr);
        while (m) {
            const int src = __ffs(m) - 1; m &= m - 1;
            const int cid = __shfl_sync(0xffffffffu, cid_l, src);
            const float* crow = cbl + (size_t)cid * DIM + lane * 32;
            float dot = 0.f;
#pragma unroll
            for (int v = 0; v < 8; v++) {
                float4 q = __ldg((const float4*)(crow + v * 4));
                dot += r4[v].x * q.x + r4[v].y * q.y + r4[v].z * q.z + r4[v].w * q.w;
            }
#pragma unroll
            for (int o = 16; o; o >>= 1) dot += __shfl_xor_sync(0xffffffffu, dot, o);
            const float sc = __ldg(c2p + cid) - 2.f * dot;
            if (sc < bestv || (sc == bestv && cid < besti)) { bestv = sc; besti = cid; }
        }
    }

    // ---- fused update (per-8-dim groups; short register lifetimes) ----
    const float* qrow = cbl + (size_t)besti * DIM + lane * 32;
    float* sums = g_sums + ((size_t)(level * KCODES + besti)) * DIM + lane * 32;
    const float* zrow = z_e + (size_t)tok * DIM + lane * 32;
    float* zo = out_zq + (size_t)tok * DIM + lane * 32;
    u16* ao = g_ah + (size_t)tok * DIM + lane * 32;
    u16* lo = g_al + (size_t)tok * DIM + lane * 32;

    float ls = 0.f;
#pragma unroll
    for (int g = 0; g < 4; g++) {
        float4 q0 = __ldg((const float4*)(qrow + g * 8));
        float4 q1 = __ldg((const float4*)(qrow + g * 8 + 4));
        float4 ra = r4[2 * g], rb = r4[2 * g + 1];
        float4 rq0 = make_float4(ra.x - q0.x, ra.y - q0.y, ra.z - q0.z, ra.w - q0.w);
        float4 rq1 = make_float4(rb.x - q1.x, rb.y - q1.y, rb.z - q1.z, rb.w - q1.w);
        ls += rq0.x * rq0.x + rq0.y * rq0.y + rq0.z * rq0.z + rq0.w * rq0.w
            + rq1.x * rq1.x + rq1.y * rq1.y + rq1.z * rq1.z + rq1.w * rq1.w;
        if (level < 2) {
            H8 ph, pl;
            split2(rq0.x, ph.s[0], pl.s[0]);
            split2(rq0.y, ph.s[1], pl.s[1]);
            split2(rq0.z, ph.s[2], pl.s[2]);
            split2(rq0.w, ph.s[3], pl.s[3]);
            split2(rq1.x, ph.s[4], pl.s[4]);
            split2(rq1.y, ph.s[5], pl.s[5]);
            split2(rq1.z, ph.s[6], pl.s[6]);
            split2(rq1.w, ph.s[7], pl.s[7]);
            *(uint4*)(ao + g * 8) = ph.v;
            *(uint4*)(lo + g * 8) = pl.v;
        } else {
            float4 z0 = __ldg((const float4*)(zrow + g * 8));
            float4 z1 = __ldg((const float4*)(zrow + g * 8 + 4));
            *(float4*)(zo + g * 8)     = make_float4(z0.x - rq0.x, z0.y - rq0.y, z0.z - rq0.z, z0.w - rq0.w);
            *(float4*)(zo + g * 8 + 4) = make_float4(z1.x - rq1.x, z1.y - rq1.y, z1.z - rq1.z, z1.w - rq1.w);
        }
        red4(sums + g * 8, ra);
        red4(sums + g * 8 + 4, rb);
    }
    if (lane == 0) {
        atomicAdd(g_counts + level * KCODES + besti, 1.0f);
        out_idx[(size_t)level * NTOK + tok] = (float)besti;
    }

    // block loss reduction -> one double atomic
#pragma unroll
    for (int o = 16; o; o >>= 1) ls += __shfl_xor_sync(0xffffffffu, ls, o);
    __shared__ float red[8];
    if (lane == 0) red[wid] = ls;
    __syncthreads();
    if (threadIdx.x < 8) {
        float v = red[threadIdx.x];
#pragma unroll
        for (int o = 4; o; o >>= 1) v += __shfl_xor_sync(0xffu, v, o);
        if (threadIdx.x == 0) atomicAdd(&g_loss_acc[level], (double)v);
    }
}

// ---------------------------------------------------------------- cs + n
__global__ void k_csn(const float* __restrict__ ema_cluster) {
    const int l = blockIdx.x;
    const int k = threadIdx.x;   // 512 threads
    float cs = DECAY * ema_cluster[l * KCODES + k] + OMD * g_counts[l * KCODES + k];
    g_cs[l * KCODES + k] = cs;
    float s = cs;
#pragma unroll
    for (int o = 16; o; o >>= 1) s += __shfl_xor_sync(0xffffffffu, s, o);
    __shared__ float red[16];
    const int warp = threadIdx.x >> 5, lane = threadIdx.x & 31;
    if (lane == 0) red[warp] = s;
    __syncthreads();
    if (threadIdx.x < 16) {
        float v = red[threadIdx.x];
#pragma unroll
        for (int o = 8; o; o >>= 1) v += __shfl_xor_sync(0xffffu, v, o);
        if (threadIdx.x == 0) g_n[l] = v;
    }
}

// ---------------------------------------------------------------- new codebooks + loss
__global__ void k_cb(const float* __restrict__ ema_w,
                     float* __restrict__ out_cb,
                     float* __restrict__ out_loss) {
    const int i = blockIdx.x * blockDim.x + threadIdx.x;
    if (i == 0) {
        double L = (0.25 * g_loss_acc[0] + 0.5 * g_loss_acc[1] + 1.0 * g_loss_acc[2])
                   * (1.0 / ((double)NTOK * (double)DIM));
        *out_loss = (float)L;
    }
    if (i >= NLEV * KCODES * DIM) return;
    const int row = i >> 10;
    const int l   = row >> 9;
    float w  = DECAY * ema_w[i] + OMD * g_sums[i];
    float cs = g_cs[row];
    float n  = g_n[l];
    float csn = (cs + EPSV) / (n + 0.00512f) * n;   // K*EPS = 512e-5
    out_cb[i] = w / csn;
}

// ---------------------------------------------------------------- launch
extern "C" void kernel_launch(void* const* d_in, const int* in_sizes, int n_in,
                              void* d_out, int out_size) {
    const float* z_e         = (const float*)d_in[0];
    const float* codebooks   = (const float*)d_in[1];
    const float* ema_cluster = (const float*)d_in[2];
    const float* ema_w       = (const float*)d_in[3];
    float* out = (float*)d_out;

    const size_t ZQ = (size_t)NTOK * DIM;
    float* out_zq   = out;
    float* out_loss = out + ZQ;
    float* out_idx  = out + ZQ + 1;
    float* out_cb   = out + ZQ + 1 + (size_t)NLEV * NTOK;

    cudaFuncSetAttribute(k_score, cudaFuncAttributeMaxDynamicSharedMemorySize, SMEM_SCORE);

    k_zero<<<(NLEV * KCODES * DIM + 255) / 256, 256>>>();
    k_cbsplit<<<NLEV * KCODES, 128>>>(codebooks);
    for (int l = 0; l < NLEV; l++) {
        k_score<<<NTOK / 64, 256, SMEM_SCORE>>>(l, z_e);
        k_pick<<<NTOK / 8, 256>>>(l, z_e, codebooks, out_zq, out_idx);
    }
    k_csn<<<NLEV, 512>>>(ema_cluster);
    k_cb<<<(NLEV * KCODES * DIM + 255) / 256, 256>>>(ema_w, out_cb, out_loss);
}

// round 16
// speedup vs baseline: 1.5212x; 1.4759x over previous
#include <cuda_runtime.h>
#include <cuda_fp16.h>
#include <cstdint>

#define NLEV   3
#define KCODES 512
#define DIM    1024
#define NTOK   65536           // 16 * 4096
#define DECAY  0.99f
#define OMD    0.01f
#define EPSV   1e-5f

typedef unsigned long long ull;
typedef unsigned int       u32;
typedef unsigned short     u16;

// ---- scratch (__device__ globals: the sanctioned no-alloc path) ----
static __device__ __align__(16) u16   g_ah[(size_t)NTOK * DIM];         // 134 MB fp16 hi(resid)
static __device__ __align__(16) u16   g_al[(size_t)NTOK * DIM];         // 134 MB fp16 lo(resid)
static __device__ __align__(16) u16   g_cbh[NLEV * KCODES * DIM];       // 3 MB fp16 hi
static __device__ __align__(16) u16   g_scoreh[(size_t)NTOK * KCODES];  // 67 MB fp16 scores
static __device__ __align__(16) float g_sums[NLEV * KCODES * DIM];      // 6 MB
static __device__ float  g_counts[NLEV * KCODES];
static __device__ float  g_c2[NLEV * KCODES];
static __device__ u32    g_c2max[NLEV];
static __device__ float  g_cs[NLEV * KCODES];
static __device__ float  g_n[NLEV];
static __device__ double g_loss_acc[NLEV];

__device__ __forceinline__ u32 smem_u32(const void* p) {
    u32 a;
    asm("{ .reg .u64 t; cvta.to.shared.u64 t, %1; cvt.u32.u64 %0, t; }" : "=r"(a) : "l"(p));
    return a;
}
__device__ __forceinline__ void red4(float* p, float4 v) {
    asm volatile("red.global.add.v4.f32 [%0], {%1,%2,%3,%4};"
                 :: "l"(p), "f"(v.x), "f"(v.y), "f"(v.z), "f"(v.w) : "memory");
}
__device__ __forceinline__ void ldsm4(u32& r0, u32& r1, u32& r2, u32& r3, u32 addr) {
    asm volatile("ldmatrix.sync.aligned.m8n8.x4.shared.b16 {%0,%1,%2,%3}, [%4];"
                 : "=r"(r0), "=r"(r1), "=r"(r2), "=r"(r3) : "r"(addr));
}
__device__ __forceinline__ void mma16816(float* c, const u32* a, const u32* b) {
    asm volatile("mma.sync.aligned.m16n8k16.row.col.f32.f16.f16.f32 "
                 "{%0,%1,%2,%3}, {%4,%5,%6,%7}, {%8,%9}, {%0,%1,%2,%3};"
                 : "+f"(c[0]), "+f"(c[1]), "+f"(c[2]), "+f"(c[3])
                 : "r"(a[0]), "r"(a[1]), "r"(a[2]), "r"(a[3]), "r"(b[0]), "r"(b[1]));
}
__device__ __forceinline__ void cp16(void* s, const void* g) {
    u32 a = smem_u32(s);
    asm volatile("cp.async.cg.shared.global [%0], [%1], 16;" :: "r"(a), "l"(g));
}
__device__ __forceinline__ void cp_commit() { asm volatile("cp.async.commit_group;"); }
__device__ __forceinline__ void cp_wait1()  { asm volatile("cp.async.wait_group 1;"); }
__device__ __forceinline__ void cp_wait0()  { asm volatile("cp.async.wait_group 0;"); }
// 2-way fp16 split: x = hi + lo exactly to ~2^-22
__device__ __forceinline__ void split2(float x, u16& h, u16& l) {
    __half hh = __float2half_rn(x);
    __half ll = __float2half_rn(x - __half2float(hh));
    h = __half_as_ushort(hh); l = __half_as_ushort(ll);
}
union H8 { u16 s[8]; uint4 v; };
union H4 { u16 s[4]; uint2 v; };

// ---------------------------------------------------------------- zero scratch
__global__ void k_zero() {
    int i = blockIdx.x * blockDim.x + threadIdx.x;
    if (i < NLEV * KCODES * DIM) g_sums[i] = 0.f;
    if (i < NLEV * KCODES)       g_counts[i] = 0.f;
    if (i < NLEV)                { g_loss_acc[i] = 0.0; g_c2max[i] = 0u; }
}

// ------------------------------------------------ codebook fp16-hi + ||C||^2 + max
__global__ void k_cbsplit(const float* __restrict__ codebooks) {
    const int row = blockIdx.x;            // NLEV*KCODES
    const int e0  = threadIdx.x * 8;       // 128 threads
    const float* src = codebooks + (size_t)row * DIM + e0;
    float4 v0 = *(const float4*)src;
    float4 v1 = *(const float4*)(src + 4);
    float xs[8] = {v0.x, v0.y, v0.z, v0.w, v1.x, v1.y, v1.z, v1.w};
    H8 ph;
    float s = 0.f;
#pragma unroll
    for (int i = 0; i < 8; i++) {
        s += xs[i] * xs[i];
        ph.s[i] = __half_as_ushort(__float2half_rn(xs[i]));
    }
    *(uint4*)(g_cbh + (size_t)row * DIM + e0) = ph.v;
#pragma unroll
    for (int o = 16; o; o >>= 1) s += __shfl_xor_sync(0xffffffffu, s, o);
    __shared__ float red[4];
    if ((threadIdx.x & 31) == 0) red[threadIdx.x >> 5] = s;
    __syncthreads();
    if (threadIdx.x == 0) {
        float c2 = red[0] + red[1] + red[2] + red[3];
        g_c2[row] = c2;
        atomicMax(&g_c2max[row >> 9], __float_as_uint(c2));   // c2 >= 0
    }
}

// ---------------------------------------------------------------- phase 1: hh scores
// Block: 64 tokens x 512 codes (4 ct tiles of 128). 8 warps: mw=wid&1 (32-token
// slice), nw=wid>>1 (32-code slice). cp.async double-buffered 64-k chunks.
// Level 0 stages A from z_e (f32) with LDG+cvt+STS; levels 1-2 from g_ah.
#define ASTRIDE 72
#define SA_ELE (64 * ASTRIDE)      // 4608 halves
#define SB_ELE (128 * ASTRIDE)     // 9216 halves
#define BUF_ELE (SA_ELE + SB_ELE)  // 13824 halves = 27648 B
#define SMEM_SCORE (2 * BUF_ELE * 2)   // 55296 B

__global__ void __launch_bounds__(256, 3) k_score(int level, const float* __restrict__ z_e) {
    extern __shared__ __align__(16) u16 dsm[];

    const int tid = threadIdx.x, wid = tid >> 5, lane = tid & 31;
    const int mw = wid & 1, nw = wid >> 1;
    const int t0 = blockIdx.x * 64;
    const bool lvl0 = (level == 0);

    const u16* bh = g_cbh + (size_t)level * KCODES * DIM;
    const float* c2p = g_c2 + level * KCODES;

    const int srow = tid >> 3, sg = tid & 7;

    // ldmatrix addressing
    const int aro = mw * 32 + (lane & 15);         // + mg*16
    const int aco = (lane >> 4) * 8;               // + k0
    const int matid = lane >> 3;
    const int selj = matid >> 1, selk = matid & 1;
    const int bro = nw * 32 + selj * 8 + (lane & 7);  // + jp*16
    const int bco = selk * 8;                          // + k0

    // stage chunk it = ct*16 + kc into buffer b
    auto stage = [&](int it, int b) {
        const int ct = it >> 4, d0 = (it & 15) * 64;
        u16* bufA = dsm + b * BUF_ELE;
        u16* bufB = bufA + SA_ELE;
        if (lvl0) {
#pragma unroll
            for (int i = 0; i < 2; i++) {
                int r = srow + i * 32;
                const float* src = z_e + (size_t)(t0 + r) * DIM + d0 + sg * 8;
                float4 v0 = __ldg((const float4*)src);
                float4 v1 = __ldg((const float4*)(src + 4));
                H8 ph;
                ph.s[0] = __half_as_ushort(__float2half_rn(v0.x));
                ph.s[1] = __half_as_ushort(__float2half_rn(v0.y));
                ph.s[2] = __half_as_ushort(__float2half_rn(v0.z));
                ph.s[3] = __half_as_ushort(__float2half_rn(v0.w));
                ph.s[4] = __half_as_ushort(__float2half_rn(v1.x));
                ph.s[5] = __half_as_ushort(__float2half_rn(v1.y));
                ph.s[6] = __half_as_ushort(__float2half_rn(v1.z));
                ph.s[7] = __half_as_ushort(__float2half_rn(v1.w));
                *(uint4*)&bufA[r * ASTRIDE + sg * 8] = ph.v;
            }
        } else {
#pragma unroll
            for (int i = 0; i < 2; i++) {
                int r = srow + i * 32;
                cp16(&bufA[r * ASTRIDE + sg * 8], g_ah + (size_t)(t0 + r) * DIM + d0 + sg * 8);
            }
        }
#pragma unroll
        for (int i = 0; i < 4; i++) {
            int r = srow + i * 32;
            cp16(&bufB[r * ASTRIDE + sg * 8], bh + (size_t)(ct * 128 + r) * DIM + d0 + sg * 8);
        }
        cp_commit();
    };

    float c[2][4][4];
#pragma unroll
    for (int mg = 0; mg < 2; mg++)
#pragma unroll
        for (int ng = 0; ng < 4; ng++)
#pragma unroll
            for (int q = 0; q < 4; q++) c[mg][ng][q] = 0.f;

    stage(0, 0);

    for (int it = 0; it < 64; it++) {
        const int b = it & 1;
        if (it + 1 < 64) { stage(it + 1, b ^ 1); cp_wait1(); } else { cp_wait0(); }
        __syncthreads();                        // buffer b ready for all warps

        const u32 aA = smem_u32(dsm + b * BUF_ELE);
        const u32 aB = smem_u32(dsm + b * BUF_ELE + SA_ELE);
#pragma unroll
        for (int kk = 0; kk < 4; kk++) {
            const int k0 = kk * 16;
            u32 Am[2][4];
#pragma unroll
            for (int mg = 0; mg < 2; mg++)
                ldsm4(Am[mg][0], Am[mg][1], Am[mg][2], Am[mg][3],
                      aA + (u32)(((aro + mg * 16) * ASTRIDE + aco + k0) * 2));
#pragma unroll
            for (int jp = 0; jp < 2; jp++) {
                u32 Bf[4];
                ldsm4(Bf[0], Bf[1], Bf[2], Bf[3],
                      aB + (u32)(((bro + jp * 16) * ASTRIDE + bco + k0) * 2));
#pragma unroll
                for (int mg = 0; mg < 2; mg++) {
                    mma16816(c[mg][2 * jp],     Am[mg], &Bf[0]);
                    mma16816(c[mg][2 * jp + 1], Am[mg], &Bf[2]);
                }
            }
        }

        if ((it & 15) == 15) {
            // epilogue for this 128-code tile: fp16 scores
            const int ct = it >> 4;
#pragma unroll
            for (int mg = 0; mg < 2; mg++) {
                const int row0 = t0 + mw * 32 + mg * 16 + (lane >> 2);
#pragma unroll
                for (int ng = 0; ng < 4; ng++) {
                    const int id = ct * 128 + nw * 32 + ng * 8 + 2 * (lane & 3);
                    const float c2a = __ldg(c2p + id);
                    const float c2b = __ldg(c2p + id + 1);
                    __half2 pa = __floats2half2_rn(c2a - 2.f * c[mg][ng][0], c2b - 2.f * c[mg][ng][1]);
                    __half2 pb = __floats2half2_rn(c2a - 2.f * c[mg][ng][2], c2b - 2.f * c[mg][ng][3]);
                    *(u32*)(g_scoreh + (size_t)row0 * KCODES + id)       = *(u32*)&pa;
                    *(u32*)(g_scoreh + (size_t)(row0 + 8) * KCODES + id) = *(u32*)&pb;
#pragma unroll
                    for (int q = 0; q < 4; q++) c[mg][ng][q] = 0.f;
                }
            }
        }
        __syncthreads();                        // all reads of buffer b done
    }
}

// ---------------------------------------------------------------- phase 2: pick + update (fused)
// One warp per token. Lane owns dims {v*128 + lane*4 .. +4} for v in [0,8):
// every fp32 access is a warp-contiguous 512B transaction (4 L1 wavefronts),
// every fp16 hi/lo access a warp-contiguous 256B uint2 (vs. 128B-strided before).
__global__ void __launch_bounds__(256, 3) k_pick(int level,
                                                 const float* __restrict__ z_e,
                                                 const float* __restrict__ codebooks,
                                                 float* __restrict__ out_zq,
                                                 float* __restrict__ out_idx) {
    const int wid = threadIdx.x >> 5, lane = threadIdx.x & 31;
    const int tok = blockIdx.x * 8 + wid;
    const float* c2p = g_c2 + level * KCODES;
    const float* cbl = codebooks + (size_t)level * KCODES * DIM;
    const u16* srow = g_scoreh + (size_t)tok * KCODES;
    const int dof = lane * 4;              // lane dim offset within each 128-dim group

    // scores: lane covers codes {i*256 + lane*8 + 0..7}, i in {0,1} -> 2 uint4 loads
    float s[16];
    float mv = 3.4e38f; int mi = 0;
#pragma unroll
    for (int i = 0; i < 2; i++) {
        uint4 pv = *(const uint4*)(srow + i * 256 + lane * 8);
        const u32 w[4] = {pv.x, pv.y, pv.z, pv.w};
        const int c0 = i * 256 + lane * 8;
#pragma unroll
        for (int h = 0; h < 4; h++) {
            float2 f = __half22float2(*(const __half2*)&w[h]);
            s[i * 8 + 2 * h]     = f.x;
            s[i * 8 + 2 * h + 1] = f.y;
            const int ca = c0 + 2 * h;
            if (f.x < mv || (f.x == mv && ca     < mi)) { mv = f.x; mi = ca; }
            if (f.y < mv || (f.y == mv && ca + 1 < mi)) { mv = f.y; mi = ca + 1; }
        }
    }
#pragma unroll
    for (int o = 16; o; o >>= 1) {
        float ov = __shfl_xor_sync(0xffffffffu, mv, o);
        int   oi = __shfl_xor_sync(0xffffffffu, mi, o);
        if (ov < mv || (ov == mv && oi < mi)) { mv = ov; mi = oi; }
    }

    // residual: interleaved dims v*128 + dof
    float4 r4[8];
    float r2 = 0.f;
    if (level == 0) {
        const float* rin = z_e + (size_t)tok * DIM + dof;
#pragma unroll
        for (int v = 0; v < 8; v++) r4[v] = *(const float4*)(rin + v * 128);
    } else {
        const u16* ap = g_ah + (size_t)tok * DIM + dof;
        const u16* lp = g_al + (size_t)tok * DIM + dof;
#pragma unroll
        for (int v = 0; v < 8; v++) {
            uint2 hv = *(const uint2*)(ap + v * 128);
            uint2 lv = *(const uint2*)(lp + v * 128);
            float2 a0 = __half22float2(*(const __half2*)&hv.x);
            float2 a1 = __half22float2(*(const __half2*)&hv.y);
            float2 b0 = __half22float2(*(const __half2*)&lv.x);
            float2 b1 = __half22float2(*(const __half2*)&lv.y);
            r4[v] = make_float4(a0.x + b0.x, a0.y + b0.y, a1.x + b1.x, a1.y + b1.y);
        }
    }
#pragma unroll
    for (int v = 0; v < 8; v++)
        r2 += r4[v].x * r4[v].x + r4[v].y * r4[v].y + r4[v].z * r4[v].z + r4[v].w * r4[v].w;
#pragma unroll
    for (int o = 16; o; o >>= 1) r2 += __shfl_xor_sync(0xffffffffu, r2, o);

    // rigorous margin: 2*eps_hh + 2q*(|mv|+8) + fp32-accum slop
    const float c2mx = __uint_as_float(g_c2max[level]);
    const float cmax = sqrtf(c2mx);
    const float rn   = sqrtf(r2);
    const float thr  = mv + 0.0039f * rn * cmax + 0.000977f * (fabsf(mv) + 8.f) + 0.25f;

    // exact rescore of candidates (contiguous codebook reads)
    float bestv = 3.4e38f; int besti = 0;
#pragma unroll
    for (int i = 0; i < 16; i++) {
        const int cid_l = (i >> 3) * 256 + lane * 8 + (i & 7);
        u32 m = __ballot_sync(0xffffffffu, s[i] <= thr);
        while (m) {
            const int src = __ffs(m) - 1; m &= m - 1;
            const int cid = __shfl_sync(0xffffffffu, cid_l, src);
            const float* crow = cbl + (size_t)cid * DIM + dof;
            float dot = 0.f;
#pragma unroll
            for (int v = 0; v < 8; v++) {
                float4 q = __ldg((const float4*)(crow + v * 128));
                dot += r4[v].x * q.x + r4[v].y * q.y + r4[v].z * q.z + r4[v].w * q.w;
            }
#pragma unroll
            for (int o = 16; o; o >>= 1) dot += __shfl_xor_sync(0xffffffffu, dot, o);
            const float sc = __ldg(c2p + cid) - 2.f * dot;
            if (sc < bestv || (sc == bestv && cid < besti)) { bestv = sc; besti = cid; }
        }
    }

    // ---- fused update (interleaved dims; all accesses warp-contiguous) ----
    const float* qrow = cbl + (size_t)besti * DIM + dof;
    float* sums = g_sums + ((size_t)(level * KCODES + besti)) * DIM + dof;
    const float* zrow = z_e + (size_t)tok * DIM + dof;
    float* zo = out_zq + (size_t)tok * DIM + dof;
    u16* ao = g_ah + (size_t)tok * DIM + dof;
    u16* lo = g_al + (size_t)tok * DIM + dof;

    float ls = 0.f;
#pragma unroll
    for (int v = 0; v < 8; v++) {
        float4 q = __ldg((const float4*)(qrow + v * 128));
        float4 r = r4[v];
        float4 rq = make_float4(r.x - q.x, r.y - q.y, r.z - q.z, r.w - q.w);
        ls += rq.x * rq.x + rq.y * rq.y + rq.z * rq.z + rq.w * rq.w;
        if (level < 2) {
            H4 ph, pl;
            split2(rq.x, ph.s[0], pl.s[0]);
            split2(rq.y, ph.s[1], pl.s[1]);
            split2(rq.z, ph.s[2], pl.s[2]);
            split2(rq.w, ph.s[3], pl.s[3]);
            *(uint2*)(ao + v * 128) = ph.v;
            *(uint2*)(lo + v * 128) = pl.v;
        } else {
            float4 ze = __ldg((const float4*)(zrow + v * 128));
            *(float4*)(zo + v * 128) = make_float4(ze.x - rq.x, ze.y - rq.y, ze.z - rq.z, ze.w - rq.w);
        }
        red4(sums + v * 128, r);
    }
    if (lane == 0) {
        atomicAdd(g_counts + level * KCODES + besti, 1.0f);
        out_idx[(size_t)level * NTOK + tok] = (float)besti;
    }

    // block loss reduction -> one double atomic
#pragma unroll
    for (int o = 16; o; o >>= 1) ls += __shfl_xor_sync(0xffffffffu, ls, o);
    __shared__ float red[8];
    if (lane == 0) red[wid] = ls;
    __syncthreads();
    if (threadIdx.x < 8) {
        float v = red[threadIdx.x];
#pragma unroll
        for (int o = 4; o; o >>= 1) v += __shfl_xor_sync(0xffu, v, o);
        if (threadIdx.x == 0) atomicAdd(&g_loss_acc[level], (double)v);
    }
}

// ---------------------------------------------------------------- cs + n
__global__ void k_csn(const float* __restrict__ ema_cluster) {
    const int l = blockIdx.x;
    const int k = threadIdx.x;   // 512 threads
    float cs = DECAY * ema_cluster[l * KCODES + k] + OMD * g_counts[l * KCODES + k];
    g_cs[l * KCODES + k] = cs;
    float s = cs;
#pragma unroll
    for (int o = 16; o; o >>= 1) s += __shfl_xor_sync(0xffffffffu, s, o);
    __shared__ float red[16];
    const int warp = threadIdx.x >> 5, lane = threadIdx.x & 31;
    if (lane == 0) red[warp] = s;
    __syncthreads();
    if (threadIdx.x < 16) {
        float v = red[threadIdx.x];
#pragma unroll
        for (int o = 8; o; o >>= 1) v += __shfl_xor_sync(0xffffu, v, o);
        if (threadIdx.x == 0) g_n[l] = v;
    }
}

// ---------------------------------------------------------------- new codebooks + loss
__global__ void k_cb(const float* __restrict__ ema_w,
                     float* __restrict__ out_cb,
                     float* __restrict__ out_loss) {
    const int i = blockIdx.x * blockDim.x + threadIdx.x;
    if (i == 0) {
        double L = (0.25 * g_loss_acc[0] + 0.5 * g_loss_acc[1] + 1.0 * g_loss_acc[2])
                   * (1.0 / ((double)NTOK * (double)DIM));
        *out_loss = (float)L;
    }
    if (i >= NLEV * KCODES * DIM) return;
    const int row = i >> 10;
    const int l   = row >> 9;
    float w  = DECAY * ema_w[i] + OMD * g_sums[i];
    float cs = g_cs[row];
    float n  = g_n[l];
    float csn = (cs + EPSV) / (n + 0.00512f) * n;   // K*EPS = 512e-5
    out_cb[i] = w / csn;
}

// ---------------------------------------------------------------- launch
extern "C" void kernel_launch(void* const* d_in, const int* in_sizes, int n_in,
                              void* d_out, int out_size) {
    const float* z_e         = (const float*)d_in[0];
    const float* codebooks   = (const float*)d_in[1];
    const float* ema_cluster = (const float*)d_in[2];
    const float* ema_w       = (const float*)d_in[3];
    float* out = (float*)d_out;

    const size_t ZQ = (size_t)NTOK * DIM;
    float* out_zq   = out;
    float* out_loss = out + ZQ;
    float* out_idx  = out + ZQ + 1;
    float* out_cb   = out + ZQ + 1 + (size_t)NLEV * NTOK;

    cudaFuncSetAttribute(k_score, cudaFuncAttributeMaxDynamicSharedMemorySize, SMEM_SCORE);

    k_zero<<<(NLEV * KCODES * DIM + 255) / 256, 256>>>();
    k_cbsplit<<<NLEV * KCODES, 128>>>(codebooks);
    for (int l = 0; l < NLEV; l++) {
        k_score<<<NTOK / 64, 256, SMEM_SCORE>>>(l, z_e);
        k_pick<<<NTOK / 8, 256>>>(l, z_e, codebooks, out_zq, out_idx);
    }
    k_csn<<<NLEV, 512>>>(ema_cluster);
    k_cb<<<(NLEV * KCODES * DIM + 255) / 256, 256>>>(ema_w, out_cb, out_loss);
}

// round 17
// speedup vs baseline: 1.6585x; 1.0902x over previous
#include <cuda_runtime.h>
#include <cuda_fp16.h>
#include <cstdint>

#define NLEV   3
#define KCODES 512
#define DIM    1024
#define NTOK   65536           // 16 * 4096
#define DECAY  0.99f
#define OMD    0.01f
#define EPSV   1e-5f

typedef unsigned long long ull;
typedef unsigned int       u32;
typedef unsigned short     u16;

// ---- scratch (__device__ globals: the sanctioned no-alloc path) ----
static __device__ __align__(16) u16   g_ah[(size_t)NTOK * DIM];         // 134 MB fp16 hi(resid)
static __device__ __align__(16) u16   g_al[(size_t)NTOK * DIM];         // 134 MB fp16 lo(resid)
static __device__ __align__(16) u16   g_cbh[NLEV * KCODES * DIM];       // 3 MB fp16 hi
static __device__ __align__(16) u16   g_scoreh[(size_t)NTOK * KCODES];  // 67 MB fp16 scores
static __device__ __align__(16) float g_sums[NLEV * KCODES * DIM];      // 6 MB
static __device__ float  g_counts[NLEV * KCODES];
static __device__ float  g_c2[NLEV * KCODES];
static __device__ u32    g_c2max[NLEV];
static __device__ float  g_cs[NLEV * KCODES];
static __device__ float  g_n[NLEV];
static __device__ double g_loss_acc[NLEV];

__device__ __forceinline__ u32 smem_u32(const void* p) {
    u32 a;
    asm("{ .reg .u64 t; cvta.to.shared.u64 t, %1; cvt.u32.u64 %0, t; }" : "=r"(a) : "l"(p));
    return a;
}
__device__ __forceinline__ void red4(float* p, float4 v) {
    asm volatile("red.global.add.v4.f32 [%0], {%1,%2,%3,%4};"
                 :: "l"(p), "f"(v.x), "f"(v.y), "f"(v.z), "f"(v.w) : "memory");
}
__device__ __forceinline__ void ldsm4(u32& r0, u32& r1, u32& r2, u32& r3, u32 addr) {
    asm volatile("ldmatrix.sync.aligned.m8n8.x4.shared.b16 {%0,%1,%2,%3}, [%4];"
                 : "=r"(r0), "=r"(r1), "=r"(r2), "=r"(r3) : "r"(addr));
}
__device__ __forceinline__ void mma16816(float* c, const u32* a, const u32* b) {
    asm volatile("mma.sync.aligned.m16n8k16.row.col.f32.f16.f16.f32 "
                 "{%0,%1,%2,%3}, {%4,%5,%6,%7}, {%8,%9}, {%0,%1,%2,%3};"
                 : "+f"(c[0]), "+f"(c[1]), "+f"(c[2]), "+f"(c[3])
                 : "r"(a[0]), "r"(a[1]), "r"(a[2]), "r"(a[3]), "r"(b[0]), "r"(b[1]));
}
__device__ __forceinline__ void cp16(void* s, const void* g) {
    u32 a = smem_u32(s);
    asm volatile("cp.async.cg.shared.global [%0], [%1], 16;" :: "r"(a), "l"(g));
}
__device__ __forceinline__ void cp_commit() { asm volatile("cp.async.commit_group;"); }
__device__ __forceinline__ void cp_wait1()  { asm volatile("cp.async.wait_group 1;"); }
__device__ __forceinline__ void cp_wait0()  { asm volatile("cp.async.wait_group 0;"); }
// 2-way fp16 split: x = hi + lo exactly to ~2^-22
__device__ __forceinline__ void split2(float x, u16& h, u16& l) {
    __half hh = __float2half_rn(x);
    __half ll = __float2half_rn(x - __half2float(hh));
    h = __half_as_ushort(hh); l = __half_as_ushort(ll);
}
union H8 { u16 s[8]; uint4 v; };
union H4 { u16 s[4]; uint2 v; };

// ---------------------------------------------------------------- zero scratch
__global__ void k_zero() {
    int i = blockIdx.x * blockDim.x + threadIdx.x;
    if (i < NLEV * KCODES * DIM) g_sums[i] = 0.f;
    if (i < NLEV * KCODES)       g_counts[i] = 0.f;
    if (i < NLEV)                { g_loss_acc[i] = 0.0; g_c2max[i] = 0u; }
}

// ------------------------------------------------ codebook fp16-hi + ||C||^2 + max
__global__ void k_cbsplit(const float* __restrict__ codebooks) {
    const int row = blockIdx.x;            // NLEV*KCODES
    const int e0  = threadIdx.x * 8;       // 128 threads
    const float* src = codebooks + (size_t)row * DIM + e0;
    float4 v0 = *(const float4*)src;
    float4 v1 = *(const float4*)(src + 4);
    float xs[8] = {v0.x, v0.y, v0.z, v0.w, v1.x, v1.y, v1.z, v1.w};
    H8 ph;
    float s = 0.f;
#pragma unroll
    for (int i = 0; i < 8; i++) {
        s += xs[i] * xs[i];
        ph.s[i] = __half_as_ushort(__float2half_rn(xs[i]));
    }
    *(uint4*)(g_cbh + (size_t)row * DIM + e0) = ph.v;
#pragma unroll
    for (int o = 16; o; o >>= 1) s += __shfl_xor_sync(0xffffffffu, s, o);
    __shared__ float red[4];
    if ((threadIdx.x & 31) == 0) red[threadIdx.x >> 5] = s;
    __syncthreads();
    if (threadIdx.x == 0) {
        float c2 = red[0] + red[1] + red[2] + red[3];
        g_c2[row] = c2;
        atomicMax(&g_c2max[row >> 9], __float_as_uint(c2));   // c2 >= 0
    }
}

// ---------------------------------------------------------------- phase 1: hh scores
// Block: 64 tokens x 512 codes (2 ct tiles of 256). 8 warps: mw=wid&1 (32-token
// slice), nw=wid>>1 (64-code slice). Warp tile 32x64 (6 ldsm : 16 MMA per kk).
// cp.async double-buffered 64-k chunks; 32 iterations (half the barriers).
// Level 0 stages A from z_e (f32) with LDG+cvt+STS; levels 1-2 from g_ah.
#define ASTRIDE 72
#define SA_ELE (64 * ASTRIDE)       // 4608 halves
#define SB_ELE (256 * ASTRIDE)      // 18432 halves
#define BUF_ELE (SA_ELE + SB_ELE)   // 23040 halves = 46080 B
#define SMEM_SCORE (2 * BUF_ELE * 2)    // 92160 B

__global__ void __launch_bounds__(256, 2) k_score(int level, const float* __restrict__ z_e) {
    extern __shared__ __align__(16) u16 dsm[];

    const int tid = threadIdx.x, wid = tid >> 5, lane = tid & 31;
    const int mw = wid & 1, nw = wid >> 1;
    const int t0 = blockIdx.x * 64;
    const bool lvl0 = (level == 0);

    const u16* bh = g_cbh + (size_t)level * KCODES * DIM;
    const float* c2p = g_c2 + level * KCODES;

    const int srow = tid >> 3, sg = tid & 7;

    // ldmatrix addressing
    const int aro = mw * 32 + (lane & 15);         // + mg*16
    const int aco = (lane >> 4) * 8;               // + k0
    const int matid = lane >> 3;
    const int selj = matid >> 1, selk = matid & 1;
    const int bro = nw * 64 + selj * 8 + (lane & 7);  // + jp*16
    const int bco = selk * 8;                          // + k0

    // stage chunk it = ct*16 + kc into buffer b (A: 2 uint4/thread, B: 8)
    auto stage = [&](int it, int b) {
        const int ct = it >> 4, d0 = (it & 15) * 64;
        u16* bufA = dsm + b * BUF_ELE;
        u16* bufB = bufA + SA_ELE;
        if (lvl0) {
#pragma unroll
            for (int i = 0; i < 2; i++) {
                int r = srow + i * 32;
                const float* src = z_e + (size_t)(t0 + r) * DIM + d0 + sg * 8;
                float4 v0 = __ldg((const float4*)src);
                float4 v1 = __ldg((const float4*)(src + 4));
                H8 ph;
                ph.s[0] = __half_as_ushort(__float2half_rn(v0.x));
                ph.s[1] = __half_as_ushort(__float2half_rn(v0.y));
                ph.s[2] = __half_as_ushort(__float2half_rn(v0.z));
                ph.s[3] = __half_as_ushort(__float2half_rn(v0.w));
                ph.s[4] = __half_as_ushort(__float2half_rn(v1.x));
                ph.s[5] = __half_as_ushort(__float2half_rn(v1.y));
                ph.s[6] = __half_as_ushort(__float2half_rn(v1.z));
                ph.s[7] = __half_as_ushort(__float2half_rn(v1.w));
                *(uint4*)&bufA[r * ASTRIDE + sg * 8] = ph.v;
            }
        } else {
#pragma unroll
            for (int i = 0; i < 2; i++) {
                int r = srow + i * 32;
                cp16(&bufA[r * ASTRIDE + sg * 8], g_ah + (size_t)(t0 + r) * DIM + d0 + sg * 8);
            }
        }
#pragma unroll
        for (int i = 0; i < 8; i++) {
            int r = srow + i * 32;
            cp16(&bufB[r * ASTRIDE + sg * 8], bh + (size_t)(ct * 256 + r) * DIM + d0 + sg * 8);
        }
        cp_commit();
    };

    float c[2][8][4];
#pragma unroll
    for (int mg = 0; mg < 2; mg++)
#pragma unroll
        for (int ng = 0; ng < 8; ng++)
#pragma unroll
            for (int q = 0; q < 4; q++) c[mg][ng][q] = 0.f;

    stage(0, 0);

    for (int it = 0; it < 32; it++) {
        const int b = it & 1;
        if (it + 1 < 32) { stage(it + 1, b ^ 1); cp_wait1(); } else { cp_wait0(); }
        __syncthreads();                        // buffer b ready for all warps

        const u32 aA = smem_u32(dsm + b * BUF_ELE);
        const u32 aB = smem_u32(dsm + b * BUF_ELE + SA_ELE);
#pragma unroll
        for (int kk = 0; kk < 4; kk++) {
            const int k0 = kk * 16;
            u32 Am[2][4];
#pragma unroll
            for (int mg = 0; mg < 2; mg++)
                ldsm4(Am[mg][0], Am[mg][1], Am[mg][2], Am[mg][3],
                      aA + (u32)(((aro + mg * 16) * ASTRIDE + aco + k0) * 2));
#pragma unroll
            for (int jp = 0; jp < 4; jp++) {
                u32 Bf[4];
                ldsm4(Bf[0], Bf[1], Bf[2], Bf[3],
                      aB + (u32)(((bro + jp * 16) * ASTRIDE + bco + k0) * 2));
#pragma unroll
                for (int mg = 0; mg < 2; mg++) {
                    mma16816(c[mg][2 * jp],     Am[mg], &Bf[0]);
                    mma16816(c[mg][2 * jp + 1], Am[mg], &Bf[2]);
                }
            }
        }

        if ((it & 15) == 15) {
            // epilogue for this 256-code tile: fp16 scores
            const int ct = it >> 4;
#pragma unroll
            for (int mg = 0; mg < 2; mg++) {
                const int row0 = t0 + mw * 32 + mg * 16 + (lane >> 2);
#pragma unroll
                for (int ng = 0; ng < 8; ng++) {
                    const int id = ct * 256 + nw * 64 + ng * 8 + 2 * (lane & 3);
                    const float c2a = __ldg(c2p + id);
                    const float c2b = __ldg(c2p + id + 1);
                    __half2 pa = __floats2half2_rn(c2a - 2.f * c[mg][ng][0], c2b - 2.f * c[mg][ng][1]);
                    __half2 pb = __floats2half2_rn(c2a - 2.f * c[mg][ng][2], c2b - 2.f * c[mg][ng][3]);
                    *(u32*)(g_scoreh + (size_t)row0 * KCODES + id)       = *(u32*)&pa;
                    *(u32*)(g_scoreh + (size_t)(row0 + 8) * KCODES + id) = *(u32*)&pb;
#pragma unroll
                    for (int q = 0; q < 4; q++) c[mg][ng][q] = 0.f;
                }
            }
        }
        __syncthreads();                        // all reads of buffer b done
    }
}

// ---------------------------------------------------------------- phase 2: pick + update (fused)
// One warp per token. Lane owns dims {v*128 + lane*4 .. +4} for v in [0,8):
// all global accesses warp-contiguous (R15 layout win).
__global__ void __launch_bounds__(256, 3) k_pick(int level,
                                                 const float* __restrict__ z_e,
                                                 const float* __restrict__ codebooks,
                                                 float* __restrict__ out_zq,
                                                 float* __restrict__ out_idx) {
    const int wid = threadIdx.x >> 5, lane = threadIdx.x & 31;
    const int tok = blockIdx.x * 8 + wid;
    const float* c2p = g_c2 + level * KCODES;
    const float* cbl = codebooks + (size_t)level * KCODES * DIM;
    const u16* srow = g_scoreh + (size_t)tok * KCODES;
    const int dof = lane * 4;              // lane dim offset within each 128-dim group

    // scores: lane covers codes {i*256 + lane*8 + 0..7}, i in {0,1} -> 2 uint4 loads
    float s[16];
    float mv = 3.4e38f; int mi = 0;
#pragma unroll
    for (int i = 0; i < 2; i++) {
        uint4 pv = *(const uint4*)(srow + i * 256 + lane * 8);
        const u32 w[4] = {pv.x, pv.y, pv.z, pv.w};
        const int c0 = i * 256 + lane * 8;
#pragma unroll
        for (int h = 0; h < 4; h++) {
            float2 f = __half22float2(*(const __half2*)&w[h]);
            s[i * 8 + 2 * h]     = f.x;
            s[i * 8 + 2 * h + 1] = f.y;
            const int ca = c0 + 2 * h;
            if (f.x < mv || (f.x == mv && ca     < mi)) { mv = f.x; mi = ca; }
            if (f.y < mv || (f.y == mv && ca + 1 < mi)) { mv = f.y; mi = ca + 1; }
        }
    }
#pragma unroll
    for (int o = 16; o; o >>= 1) {
        float ov = __shfl_xor_sync(0xffffffffu, mv, o);
        int   oi = __shfl_xor_sync(0xffffffffu, mi, o);
        if (ov < mv || (ov == mv && oi < mi)) { mv = ov; mi = oi; }
    }

    // residual: interleaved dims v*128 + dof
    float4 r4[8];
    float r2 = 0.f;
    if (level == 0) {
        const float* rin = z_e + (size_t)tok * DIM + dof;
#pragma unroll
        for (int v = 0; v < 8; v++) r4[v] = *(const float4*)(rin + v * 128);
    } else {
        const u16* ap = g_ah + (size_t)tok * DIM + dof;
        const u16* lp = g_al + (size_t)tok * DIM + dof;
#pragma unroll
        for (int v = 0; v < 8; v++) {
            uint2 hv = *(const uint2*)(ap + v * 128);
            uint2 lv = *(const uint2*)(lp + v * 128);
            float2 a0 = __half22float2(*(const __half2*)&hv.x);
            float2 a1 = __half22float2(*(const __half2*)&hv.y);
            float2 b0 = __half22float2(*(const __half2*)&lv.x);
            float2 b1 = __half22float2(*(const __half2*)&lv.y);
            r4[v] = make_float4(a0.x + b0.x, a0.y + b0.y, a1.x + b1.x, a1.y + b1.y);
        }
    }
#pragma unroll
    for (int v = 0; v < 8; v++)
        r2 += r4[v].x * r4[v].x + r4[v].y * r4[v].y + r4[v].z * r4[v].z + r4[v].w * r4[v].w;
#pragma unroll
    for (int o = 16; o; o >>= 1) r2 += __shfl_xor_sync(0xffffffffu, r2, o);

    // rigorous margin: 2*eps_hh + 2q*(|mv|+8) + fp32-accum slop
    const float c2mx = __uint_as_float(g_c2max[level]);
    const float cmax = sqrtf(c2mx);
    const float rn   = sqrtf(r2);
    const float thr  = mv + 0.0039f * rn * cmax + 0.000977f * (fabsf(mv) + 8.f) + 0.25f;

    // exact rescore of candidates (contiguous codebook reads)
    float bestv = 3.4e38f; int besti = 0;
#pragma unroll
    for (int i = 0; i < 16; i++) {
        const int cid_l = (i >> 3) * 256 + lane * 8 + (i & 7);
        u32 m = __ballot_sync(0xffffffffu, s[i] <= thr);
        while (m) {
            const int src = __ffs(m) - 1; m &= m - 1;
            const int cid = __shfl_sync(0xffffffffu, cid_l, src);
            const float* crow = cbl + (size_t)cid * DIM + dof;
            float dot = 0.f;
#pragma unroll
            for (int v = 0; v < 8; v++) {
                float4 q = __ldg((const float4*)(crow + v * 128));
                dot += r4[v].x * q.x + r4[v].y * q.y + r4[v].z * q.z + r4[v].w * q.w;
            }
#pragma unroll
            for (int o = 16; o; o >>= 1) dot += __shfl_xor_sync(0xffffffffu, dot, o);
            const float sc = __ldg(c2p + cid) - 2.f * dot;
            if (sc < bestv || (sc == bestv && cid < besti)) { bestv = sc; besti = cid; }
        }
    }

    // ---- fused update (interleaved dims; all accesses warp-contiguous) ----
    const float* qrow = cbl + (size_t)besti * DIM + dof;
    float* sums = g_sums + ((size_t)(level * KCODES + besti)) * DIM + dof;
    const float* zrow = z_e + (size_t)tok * DIM + dof;
    float* zo = out_zq + (size_t)tok * DIM + dof;
    u16* ao = g_ah + (size_t)tok * DIM + dof;
    u16* lo = g_al + (size_t)tok * DIM + dof;

    float ls = 0.f;
#pragma unroll
    for (int v = 0; v < 8; v++) {
        float4 q = __ldg((const float4*)(qrow + v * 128));
        float4 r = r4[v];
        float4 rq = make_float4(r.x - q.x, r.y - q.y, r.z - q.z, r.w - q.w);
        ls += rq.x * rq.x + rq.y * rq.y + rq.z * rq.z + rq.w * rq.w;
        if (level < 2) {
            H4 ph, pl;
            split2(rq.x, ph.s[0], pl.s[0]);
            split2(rq.y, ph.s[1], pl.s[1]);
            split2(rq.z, ph.s[2], pl.s[2]);
            split2(rq.w, ph.s[3], pl.s[3]);
            *(uint2*)(ao + v * 128) = ph.v;
            *(uint2*)(lo + v * 128) = pl.v;
        } else {
            float4 ze = __ldg((const float4*)(zrow + v * 128));
            *(float4*)(zo + v * 128) = make_float4(ze.x - rq.x, ze.y - rq.y, ze.z - rq.z, ze.w - rq.w);
        }
        red4(sums + v * 128, r);
    }
    if (lane == 0) {
        atomicAdd(g_counts + level * KCODES + besti, 1.0f);
        out_idx[(size_t)level * NTOK + tok] = (float)besti;
    }

    // block loss reduction -> one double atomic
#pragma unroll
    for (int o = 16; o; o >>= 1) ls += __shfl_xor_sync(0xffffffffu, ls, o);
    __shared__ float red[8];
    if (lane == 0) red[wid] = ls;
    __syncthreads();
    if (threadIdx.x < 8) {
        float v = red[threadIdx.x];
#pragma unroll
        for (int o = 4; o; o >>= 1) v += __shfl_xor_sync(0xffu, v, o);
        if (threadIdx.x == 0) atomicAdd(&g_loss_acc[level], (double)v);
    }
}

// ---------------------------------------------------------------- cs + n
__global__ void k_csn(const float* __restrict__ ema_cluster) {
    const int l = blockIdx.x;
    const int k = threadIdx.x;   // 512 threads
    float cs = DECAY * ema_cluster[l * KCODES + k] + OMD * g_counts[l * KCODES + k];
    g_cs[l * KCODES + k] = cs;
    float s = cs;
#pragma unroll
    for (int o = 16; o; o >>= 1) s += __shfl_xor_sync(0xffffffffu, s, o);
    __shared__ float red[16];
    const int warp = threadIdx.x >> 5, lane = threadIdx.x & 31;
    if (lane == 0) red[warp] = s;
    __syncthreads();
    if (threadIdx.x < 16) {
        float v = red[threadIdx.x];
#pragma unroll
        for (int o = 8; o; o >>= 1) v += __shfl_xor_sync(0xffffu, v, o);
        if (threadIdx.x == 0) g_n[l] = v;
    }
}

// ---------------------------------------------------------------- new codebooks + loss
__global__ void k_cb(const float* __restrict__ ema_w,
                     float* __restrict__ out_cb,
                     float* __restrict__ out_loss) {
    const int i = blockIdx.x * blockDim.x + threadIdx.x;
    if (i == 0) {
        double L = (0.25 * g_loss_acc[0] + 0.5 * g_loss_acc[1] + 1.0 * g_loss_acc[2])
                   * (1.0 / ((double)NTOK * (double)DIM));
        *out_loss = (float)L;
    }
    if (i >= NLEV * KCODES * DIM) return;
    const int row = i >> 10;
    const int l   = row >> 9;
    float w  = DECAY * ema_w[i] + OMD * g_sums[i];
    float cs = g_cs[row];
    float n  = g_n[l];
    float csn = (cs + EPSV) / (n + 0.00512f) * n;   // K*EPS = 512e-5
    out_cb[i] = w / csn;
}

// ---------------------------------------------------------------- launch
extern "C" void kernel_launch(void* const* d_in, const int* in_sizes, int n_in,
                              void* d_out, int out_size) {
    const float* z_e         = (const float*)d_in[0];
    const float* codebooks   = (const float*)d_in[1];
    const float* ema_cluster = (const float*)d_in[2];
    const float* ema_w       = (const float*)d_in[3];
    float* out = (float*)d_out;

    const size_t ZQ = (size_t)NTOK * DIM;
    float* out_zq   = out;
    float* out_loss = out + ZQ;
    float* out_idx  = out + ZQ + 1;
    float* out_cb   = out + ZQ + 1 + (size_t)NLEV * NTOK;

    cudaFuncSetAttribute(k_score, cudaFuncAttributeMaxDynamicSharedMemorySize, SMEM_SCORE);

    k_zero<<<(NLEV * KCODES * DIM + 255) / 256, 256>>>();
    k_cbsplit<<<NLEV * KCODES, 128>>>(codebooks);
    for (int l = 0; l < NLEV; l++) {
        k_score<<<NTOK / 64, 256, SMEM_SCORE>>>(l, z_e);
        k_pick<<<NTOK / 8, 256>>>(l, z_e, codebooks, out_zq, out_idx);
    }
    k_csn<<<NLEV, 512>>>(ema_cluster);
    k_cb<<<(NLEV * KCODES * DIM + 255) / 256, 256>>>(ema_w, out_cb, out_loss);
}